// round 14
// baseline (speedup 1.0000x reference)
#include <cuda_runtime.h>
#include <cuda_fp16.h>
#include <math.h>
#include <stdint.h>

#define N_NODES 100000
#define N_EDGES 1600000
#define IN_C    128
#define HID_C   256
#define OUT_C   47
#define OUTP    48

// ---------------- scratch (static __device__, no allocs) ----------------
__device__ __align__(256) __half g_Xh[(size_t)N_NODES * IN_C];   // x fp16 (25.6MB)
__device__ __align__(256) __half g_M[(size_t)N_NODES * IN_C];    // mean(x_nbr) fp16
__device__ __align__(256) __half g_W1t[256 * 256];  // [W1l;W1r]^T fp16 (n-major)
__device__ __align__(256) __half g_W2t[96 * 256];   // padded [W2l|W2r]^T fp16
__device__ __align__(256) __half g_ylh[(size_t)N_NODES * OUTP]; // h@W2l fp16
__device__ __align__(256) float  g_yr[(size_t)N_NODES * OUTP];  // h@W2r fp32
__device__ int   g_deg[N_NODES];
__device__ int   g_off[N_NODES + 1];
__device__ int   g_cur[N_NODES];
__device__ int   g_srcs[N_EDGES];
__device__ int   g_bsum[128];
__device__ int   g_bflag[128];
__device__ int   g_is64;

// ---------------- helpers ----------------
__device__ __forceinline__ uint32_t smem_u32(const void* p) {
    uint32_t a;
    asm("{ .reg .u64 t; cvta.to.shared.u64 t, %1; cvt.u32.u64 %0, t; }" : "=r"(a) : "l"(p));
    return a;
}
__device__ __forceinline__ uint32_t swz(uint32_t o) { return o ^ ((o >> 3) & 0x70); }

__device__ __forceinline__ void ldsm4(uint32_t* r, uint32_t addr) {
    asm volatile("ldmatrix.sync.aligned.m8n8.x4.shared.b16 {%0,%1,%2,%3}, [%4];"
        : "=r"(r[0]), "=r"(r[1]), "=r"(r[2]), "=r"(r[3]) : "r"(addr));
}
__device__ __forceinline__ void mma_f16(float* c, const uint32_t* a, const uint32_t* b) {
    asm volatile("mma.sync.aligned.m16n8k16.row.col.f32.f16.f16.f32 "
        "{%0,%1,%2,%3}, {%4,%5,%6,%7}, {%8,%9}, {%0,%1,%2,%3};"
        : "+f"(c[0]), "+f"(c[1]), "+f"(c[2]), "+f"(c[3])
        : "r"(a[0]), "r"(a[1]), "r"(a[2]), "r"(a[3]), "r"(b[0]), "r"(b[1]));
}
__device__ __forceinline__ uint32_t pack_h2(__half a, __half b) {
    __half2 t; t.x = a; t.y = b;
    return *(uint32_t*)&t;
}
__device__ __forceinline__ void cp16(uint32_t sm, const void* g, bool v) {
    int sz = v ? 16 : 0;
    asm volatile("cp.async.cg.shared.global [%0], [%1], 16, %2;"
        :: "r"(sm), "l"(g), "r"(sz));
}
#define CP_COMMIT()  asm volatile("cp.async.commit_group;" ::: "memory")
#define CP_WAIT(n)   asm volatile("cp.async.wait_group %0;" :: "n"(n) : "memory")

// ---------------- edge dtype ----------------
__device__ __forceinline__ int edge_src(const void* p, int e) {
    return g_is64 ? (int)((const long long*)p)[e] : ((const int*)p)[e];
}
__device__ __forceinline__ int edge_dst(const void* p, int e) {
    return g_is64 ? (int)((const long long*)p)[N_EDGES + e] : ((const int*)p)[N_EDGES + e];
}

// ---------------- stream-B head: deg zero + scan-flag zero + dtype detect ----------------
__global__ void zero_detect_kernel(const int* __restrict__ e32) {
    int i = blockIdx.x * blockDim.x + threadIdx.x;
    if (i < N_NODES) g_deg[i] = 0;
    if (i < 128) { g_bflag[i] = 0; }
    if (i == 0) {
        int nz = 0;
        for (int q = 0; q < 64; q++) nz |= e32[2 * q + 1];
        g_is64 = (nz == 0) ? 1 : 0;
    }
}

// ---------------- fused: x->fp16 + weight transpose ----------------
#define NXT (N_NODES * 32)
__global__ void prep_convw_kernel(const float* __restrict__ x,
                                  const float* __restrict__ W1l, const float* __restrict__ W1r,
                                  const float* __restrict__ W2l, const float* __restrict__ W2r) {
    int t = blockIdx.x * blockDim.x + threadIdx.x;
    if (t < NXT) {
        int row = t >> 5, q = t & 31;
        float4 v = ((const float4*)x)[(size_t)row * 32 + q];
        *(uint2*)(g_Xh + (size_t)row * 128 + q * 4) = make_uint2(
            pack_h2(__float2half(v.x), __float2half(v.y)),
            pack_h2(__float2half(v.z), __float2half(v.w)));
    } else {
        int idx = t - NXT;
        if (idx < 256 * 256) {
            int n = idx >> 8, k = idx & 255;
            float v = (k < 128) ? W1l[(size_t)k * 256 + n] : W1r[(size_t)(k - 128) * 256 + n];
            g_W1t[idx] = __float2half(v);
        } else if (idx < 256 * 256 + 96 * 256) {
            int j = idx - 256 * 256;
            int n = j >> 8, k = j & 255;
            float v = 0.f;
            if (n < 47) v = W2l[(size_t)k * 47 + n];
            else if (n >= 48 && n < 95) v = W2r[(size_t)k * 47 + (n - 48)];
            g_W2t[j] = __float2half(v);
        }
    }
}

// ---------------- CSR build: 4-edge-per-thread batched hist & scatter ----------------
#define EB 4
__global__ void hist_kernel(const void* __restrict__ ei) {
    int base = (blockIdx.x * blockDim.x + threadIdx.x) * EB;
    if (base >= N_EDGES) return;
    int d[EB];
    int n = min(EB, N_EDGES - base);
#pragma unroll
    for (int q = 0; q < EB; q++)
        if (q < n) d[q] = edge_dst(ei, base + q);
#pragma unroll
    for (int q = 0; q < EB; q++)
        if (q < n) atomicAdd(&g_deg[d[q]], 1);
}

// single-pass scan: local block scan + publish block sum + poll predecessors.
#define SCAN_B 1024
__global__ void scan_fused_kernel() {
    __shared__ int sm[SCAN_B];
    __shared__ int base_s;
    int tid = threadIdx.x;
    int b = blockIdx.x;
    int i = b * SCAN_B + tid;
    int d = (i < N_NODES) ? g_deg[i] : 0;
    sm[tid] = d;
    __syncthreads();
    for (int off = 1; off < SCAN_B; off <<= 1) {
        int t = (tid >= off) ? sm[tid - off] : 0;
        __syncthreads();
        sm[tid] += t;
        __syncthreads();
    }
    int incl = sm[tid];
    if (tid == SCAN_B - 1) {
        g_bsum[b] = incl;
        __threadfence();
        atomicExch(&g_bflag[b], 1);
    }
    if (tid == 0) base_s = 0;
    __syncthreads();
    if (tid < b) {
        while (atomicAdd(&g_bflag[tid], 0) == 0) { }
        atomicAdd(&base_s, g_bsum[tid]);
    }
    __syncthreads();
    int base = base_s;
    if (i < N_NODES) {
        int v = incl + base;
        g_off[i + 1] = v;
        g_cur[i] = v - d;
    }
    if (i == 0) g_off[0] = 0;
}

__global__ void scatter_kernel(const void* __restrict__ ei) {
    int base = (blockIdx.x * blockDim.x + threadIdx.x) * EB;
    if (base >= N_EDGES) return;
    int s[EB], d[EB];
    int n = min(EB, N_EDGES - base);
#pragma unroll
    for (int q = 0; q < EB; q++)
        if (q < n) { s[q] = edge_src(ei, base + q); d[q] = edge_dst(ei, base + q); }
    int p[EB];
#pragma unroll
    for (int q = 0; q < EB; q++)
        if (q < n) p[q] = atomicAdd(&g_cur[d[q]], 1);
#pragma unroll
    for (int q = 0; q < EB; q++)
        if (q < n) g_srcs[p[q]] = s[q];
}

// ---------------- agg1: mean of fp16 x over in-neighbors -> g_M ----------------
__global__ void agg1_kernel() {
    int w = (blockIdx.x * blockDim.x + threadIdx.x) >> 5;
    if (w >= N_NODES) return;
    int lane = threadIdx.x & 31;
    int beg = g_off[w], end = g_off[w + 1];
    const uint2* xv = (const uint2*)g_Xh;
    float4 acc = make_float4(0.f, 0.f, 0.f, 0.f);
    for (int e0 = beg; e0 < end; e0 += 32) {
        int me = e0 + lane;
        int s = (me < end) ? g_srcs[me] : 0;
        int cnt = min(32, end - e0);
        for (int j = 0; j < cnt; j++) {
            int sj = __shfl_sync(0xffffffffu, s, j);
            uint2 p = xv[(size_t)sj * 32 + lane];
            float2 a = __half22float2(*(__half2*)&p.x);
            float2 b = __half22float2(*(__half2*)&p.y);
            acc.x += a.x; acc.y += a.y; acc.z += b.x; acc.w += b.y;
        }
    }
    float inv = 1.f / (float)max(end - beg, 1);
    *(uint2*)(g_M + (size_t)w * 128 + lane * 4) = make_uint2(
        pack_h2(__float2half(acc.x * inv), __float2half(acc.y * inv)),
        pack_h2(__float2half(acc.z * inv), __float2half(acc.w * inv)));
}

// ---------------- FUSED GEMM: H = relu([M|X]@W1^T + b1) kept in smem,
//                  then [yl|yr] = H @ W2^T  (single kernel, no H round-trip)
__global__ __launch_bounds__(256) void fused_gemm(const float* __restrict__ b1) {
    extern __shared__ __align__(1024) char smm[];
    const int BUF = 49152, AO = 0, WO = 16384;
    const int HBASE = 0, W2BASE = 65536, W2BUF = 12288;
    uint32_t sb = smem_u32(smm);
    int tid = threadIdx.x, l = tid & 31, wid = tid >> 5;
    int wm = wid & 3, wn = wid >> 2;
    int rowBase = blockIdx.x * 128;

    float acc[2][16][4];
#pragma unroll
    for (int i = 0; i < 2; i++)
#pragma unroll
        for (int j = 0; j < 16; j++)
#pragma unroll
            for (int q = 0; q < 4; q++) acc[i][j][q] = 0.f;

    int a_r0 = wm * 32 + (l & 7) + (l & 8);
    int a_kl = (l >> 4) * 8;
    int b_r0 = wn * 128 + (l & 7) + ((l >> 4) & 1) * 8;
    int b_kl = ((l >> 3) & 1) * 8;

    auto load_chunk = [&](int c, int buf) {
#pragma unroll
        for (int hh = 0; hh < 4; hh++) {
            int i = tid + hh * 256;
            int r = i >> 3, s = i & 7;
            uint32_t so = swz(r * 128 + s * 16);
            int row = rowBase + r;
            bool ok = row < N_NODES;
            int rc = ok ? row : 0;
            const char* asrc = (c < 2)
                ? ((const char*)g_M + (size_t)rc * 256 + c * 128 + s * 16)
                : ((const char*)g_Xh + (size_t)rc * 256 + (c - 2) * 128 + s * 16);
            cp16(sb + buf * BUF + AO + so, asrc, ok);
        }
#pragma unroll
        for (int hh = 0; hh < 8; hh++) {
            int i = tid + hh * 256;
            int r = i >> 3, s = i & 7;
            uint32_t so = swz(r * 128 + s * 16);
            cp16(sb + buf * BUF + WO + so,
                 (const char*)g_W1t + (size_t)r * 512 + c * 128 + s * 16, true);
        }
        CP_COMMIT();
    };

    load_chunk(0, 0);
#pragma unroll
    for (int c = 0; c < 4; c++) {
        if (c < 3) { load_chunk(c + 1, (c + 1) & 1); CP_WAIT(1); }
        else CP_WAIT(0);
        __syncthreads();
        uint32_t bbase = sb + (c & 1) * BUF;
#pragma unroll
        for (int ks = 0; ks < 4; ks++) {
            uint32_t ah[2][4];
#pragma unroll
            for (int mf = 0; mf < 2; mf++)
                ldsm4(ah[mf], bbase + AO + swz((a_r0 + mf * 16) * 128 + (ks * 16 + a_kl) * 2));
#pragma unroll
            for (int nf2 = 0; nf2 < 8; nf2++) {
                uint32_t off = swz((b_r0 + nf2 * 16) * 128 + (ks * 16 + b_kl) * 2);
                uint32_t bh[4];
                ldsm4(bh, bbase + WO + off);
#pragma unroll
                for (int half = 0; half < 2; half++) {
                    int nf = nf2 * 2 + half;
                    uint32_t bhp[2] = {bh[half * 2], bh[half * 2 + 1]};
#pragma unroll
                    for (int mf = 0; mf < 2; mf++)
                        mma_f16(acc[mf][nf], ah[mf], bhp);
                }
            }
        }
        __syncthreads();
    }

    // ---- phase 2 setup: prefetch W2 chunk 0, store H (relu+bias, fp16) to smem ----
    auto load_w2 = [&](int c, int buf) {
#pragma unroll
        for (int hh = 0; hh < 3; hh++) {
            int i = tid + hh * 256;
            int r = i >> 3, s = i & 7;
            cp16(sb + W2BASE + buf * W2BUF + swz(r * 128 + s * 16),
                 (const char*)g_W2t + (size_t)r * 512 + c * 128 + s * 16, true);
        }
        CP_COMMIT();
    };
    load_w2(0, 0);

    {
        int er0l = wm * 32 + (l >> 2);       // local row
        int ec0 = wn * 128 + (l & 3) * 2;
#pragma unroll
        for (int nf = 0; nf < 16; nf++) {
            int col = ec0 + nf * 8;
            int chunk = col >> 6;
            int k = col & 63;
            float bx = __ldg(b1 + col), by = __ldg(b1 + col + 1);
#pragma unroll
            for (int mf = 0; mf < 2; mf++) {
#pragma unroll
                for (int half = 0; half < 2; half++) {
                    int r = er0l + mf * 16 + half * 8;
                    float v0 = fmaxf(acc[mf][nf][half * 2 + 0] + bx, 0.f);
                    float v1 = fmaxf(acc[mf][nf][half * 2 + 1] + by, 0.f);
                    *(uint32_t*)(smm + HBASE + chunk * 16384 + swz(r * 128 + k * 2)) =
                        pack_h2(__float2half(v0), __float2half(v1));
                }
            }
        }
    }
    CP_WAIT(0);
    __syncthreads();

    // ---- phase 2: [yl|yr] = H @ W2^T (N=96), warp tile 32x48 ----
    float acc2[2][6][4];
#pragma unroll
    for (int i = 0; i < 2; i++)
#pragma unroll
        for (int j = 0; j < 6; j++)
#pragma unroll
            for (int q = 0; q < 4; q++) acc2[i][j][q] = 0.f;

    int b2_r0 = wn * 48 + (l & 7) + ((l >> 4) & 1) * 8;

#pragma unroll
    for (int c = 0; c < 4; c++) {
        if (c < 3) load_w2(c + 1, (c + 1) & 1);
        uint32_t hbase = sb + HBASE + c * 16384;
        uint32_t wbase = sb + W2BASE + (c & 1) * W2BUF;
#pragma unroll
        for (int ks = 0; ks < 4; ks++) {
            uint32_t ah[2][4];
#pragma unroll
            for (int mf = 0; mf < 2; mf++)
                ldsm4(ah[mf], hbase + swz((a_r0 + mf * 16) * 128 + (ks * 16 + a_kl) * 2));
#pragma unroll
            for (int nf2 = 0; nf2 < 3; nf2++) {
                uint32_t off = swz((b2_r0 + nf2 * 16) * 128 + (ks * 16 + b_kl) * 2);
                uint32_t bh[4];
                ldsm4(bh, wbase + off);
#pragma unroll
                for (int half = 0; half < 2; half++) {
                    int nf = nf2 * 2 + half;
                    uint32_t bhp[2] = {bh[half * 2], bh[half * 2 + 1]};
#pragma unroll
                    for (int mf = 0; mf < 2; mf++)
                        mma_f16(acc2[mf][nf], ah[mf], bhp);
                }
            }
        }
        if (c < 3) { CP_WAIT(0); __syncthreads(); }
    }

    // epilogue: yl (fp16) / yr (fp32)
    int er0 = rowBase + wm * 32 + (l >> 2);
    int ec0 = wn * 48 + (l & 3) * 2;
#pragma unroll
    for (int nf = 0; nf < 6; nf++) {
        int col = ec0 + nf * 8;
#pragma unroll
        for (int mf = 0; mf < 2; mf++) {
#pragma unroll
            for (int half = 0; half < 2; half++) {
                int row = er0 + mf * 16 + half * 8;
                if (row >= N_NODES) continue;
                float v0 = acc2[mf][nf][half * 2 + 0];
                float v1 = acc2[mf][nf][half * 2 + 1];
                if (col < 48)
                    *(uint32_t*)(g_ylh + (size_t)row * OUTP + col) =
                        pack_h2(__float2half(v0), __float2half(v1));
                else
                    *(float2*)(g_yr + (size_t)row * OUTP + col - 48) = make_float2(v0, v1);
            }
        }
    }
}

// ---------------- final: mean-agg of ylh (fp16) + b2 + yr + log_softmax ----------------
__global__ void final_kernel(const float* __restrict__ b2, float* __restrict__ out) {
    int w = (blockIdx.x * blockDim.x + threadIdx.x) >> 5;
    if (w >= N_NODES) return;
    int lane = threadIdx.x & 31;
    int beg = g_off[w], end = g_off[w + 1];
    float inv = 1.f / (float)max(end - beg, 1);
    bool act = lane < 24;
    const uint32_t* ylv = (const uint32_t*)g_ylh;
    float2 acc = make_float2(0.f, 0.f);
    for (int e0 = beg; e0 < end; e0 += 32) {
        int me = e0 + lane;
        int s = (me < end) ? g_srcs[me] : 0;
        int cnt = min(32, end - e0);
        for (int j = 0; j < cnt; j++) {
            int sj = __shfl_sync(0xffffffffu, s, j);
            if (act) {
                uint32_t p = ylv[(size_t)sj * 24 + lane];
                float2 v = __half22float2(*(__half2*)&p);
                acc.x += v.x; acc.y += v.y;
            }
        }
    }
    int c0 = lane * 2, c1 = lane * 2 + 1;
    float z0 = -1e30f, z1 = -1e30f;
    if (c0 < OUT_C) z0 = acc.x * inv + b2[c0] + g_yr[(size_t)w * OUTP + c0];
    if (c1 < OUT_C) z1 = acc.y * inv + b2[c1] + g_yr[(size_t)w * OUTP + c1];
    float m = fmaxf(z0, z1);
#pragma unroll
    for (int o = 16; o > 0; o >>= 1) m = fmaxf(m, __shfl_xor_sync(0xffffffffu, m, o));
    float s = 0.f;
    if (c0 < OUT_C) s += expf(z0 - m);
    if (c1 < OUT_C) s += expf(z1 - m);
#pragma unroll
    for (int o = 16; o > 0; o >>= 1) s += __shfl_xor_sync(0xffffffffu, s, o);
    float l = logf(s);
    if (c0 < OUT_C) out[(size_t)w * OUT_C + c0] = z0 - m - l;
    if (c1 < OUT_C) out[(size_t)w * OUT_C + c1] = z1 - m - l;
}

// ---------------- launch ----------------
extern "C" void kernel_launch(void* const* d_in, const int* in_sizes, int n_in,
                              void* d_out, int out_size) {
    const float* x   = (const float*)d_in[0];
    const void*  ei  = d_in[1];
    const float* W1l = (const float*)d_in[2];
    const float* b1  = (const float*)d_in[3];
    const float* W1r = (const float*)d_in[4];
    const float* W2l = (const float*)d_in[5];
    const float* b2  = (const float*)d_in[6];
    const float* W2r = (const float*)d_in[7];
    float* out = (float*)d_out;

    static cudaStream_t s2 = nullptr;
    static cudaEvent_t evF = nullptr, evS = nullptr;
    if (!s2) {
        cudaStreamCreate(&s2);
        cudaEventCreateWithFlags(&evF, cudaEventDisableTiming);
        cudaEventCreateWithFlags(&evS, cudaEventDisableTiming);
    }

    const int SMEM = 98304;
    static bool attr_set = false;
    if (!attr_set) {
        cudaFuncSetAttribute(fused_gemm, cudaFuncAttributeMaxDynamicSharedMemorySize, SMEM);
        attr_set = true;
    }

    const int scan_blocks = (N_NODES + SCAN_B - 1) / SCAN_B;   // 98
    const int tiles = (N_NODES + 127) / 128;                    // 782
    const int edge_blocks = (N_EDGES / EB + 255) / 256;         // 1563

    // fork: s2 builds CSR while stream 0 converts x and weights
    cudaEventRecord(evF, 0);
    cudaStreamWaitEvent(s2, evF, 0);

    zero_detect_kernel<<<(N_NODES + 255) / 256, 256, 0, s2>>>((const int*)ei);
    hist_kernel<<<edge_blocks, 256, 0, s2>>>(ei);
    scan_fused_kernel<<<scan_blocks, SCAN_B, 0, s2>>>();
    scatter_kernel<<<edge_blocks, 256, 0, s2>>>(ei);
    cudaEventRecord(evS, s2);           // CSR complete

    prep_convw_kernel<<<(NXT + 256 * 256 + 96 * 256 + 255) / 256, 256>>>(x, W1l, W1r, W2l, W2r);

    // join: agg needs CSR; fused gemm needs agg + prep (in-stream order)
    cudaStreamWaitEvent(0, evS, 0);
    agg1_kernel<<<(N_NODES * 32 + 255) / 256, 256>>>();
    fused_gemm<<<tiles, 256, SMEM>>>(b1);
    final_kernel<<<(N_NODES * 32 + 255) / 256, 256>>>(b2, out);
}

// round 15
// speedup vs baseline: 1.0658x; 1.0658x over previous
#include <cuda_runtime.h>
#include <cuda_fp16.h>
#include <math.h>
#include <stdint.h>

#define N_NODES 100000
#define N_EDGES 1600000
#define IN_C    128
#define HID_C   256
#define OUT_C   47
#define OUTP    48

// ---------------- scratch (static __device__, no allocs) ----------------
__device__ __align__(256) __half g_Xh[(size_t)N_NODES * IN_C];   // x fp16 (25.6MB)
__device__ __align__(256) __half g_M[(size_t)N_NODES * IN_C];    // mean(x_nbr) fp16
__device__ __align__(256) __half g_W1t[256 * 256];  // [W1l;W1r]^T fp16 (n-major)
__device__ __align__(256) __half g_W2t[96 * 256];   // padded [W2l|W2r]^T fp16
__device__ __align__(256) __half g_ylh[(size_t)N_NODES * OUTP]; // h@W2l fp16
__device__ __align__(256) float  g_yr[(size_t)N_NODES * OUTP];  // h@W2r fp32
__device__ int   g_deg[N_NODES];
__device__ int   g_off[N_NODES + 1];
__device__ int   g_cur[N_NODES];
__device__ int   g_srcs[N_EDGES];
__device__ int   g_bsum[128];
__device__ int   g_bflag[128];
__device__ int   g_is64;

// ---------------- helpers ----------------
__device__ __forceinline__ uint32_t smem_u32(const void* p) {
    uint32_t a;
    asm("{ .reg .u64 t; cvta.to.shared.u64 t, %1; cvt.u32.u64 %0, t; }" : "=r"(a) : "l"(p));
    return a;
}
__device__ __forceinline__ uint32_t swz(uint32_t o) { return o ^ ((o >> 3) & 0x70); }

__device__ __forceinline__ void ldsm4(uint32_t* r, uint32_t addr) {
    asm volatile("ldmatrix.sync.aligned.m8n8.x4.shared.b16 {%0,%1,%2,%3}, [%4];"
        : "=r"(r[0]), "=r"(r[1]), "=r"(r[2]), "=r"(r[3]) : "r"(addr));
}
__device__ __forceinline__ void mma_f16(float* c, const uint32_t* a, const uint32_t* b) {
    asm volatile("mma.sync.aligned.m16n8k16.row.col.f32.f16.f16.f32 "
        "{%0,%1,%2,%3}, {%4,%5,%6,%7}, {%8,%9}, {%0,%1,%2,%3};"
        : "+f"(c[0]), "+f"(c[1]), "+f"(c[2]), "+f"(c[3])
        : "r"(a[0]), "r"(a[1]), "r"(a[2]), "r"(a[3]), "r"(b[0]), "r"(b[1]));
}
__device__ __forceinline__ uint32_t pack_h2(__half a, __half b) {
    __half2 t; t.x = a; t.y = b;
    return *(uint32_t*)&t;
}
__device__ __forceinline__ void cp16(uint32_t sm, const void* g, bool v) {
    int sz = v ? 16 : 0;
    asm volatile("cp.async.cg.shared.global [%0], [%1], 16, %2;"
        :: "r"(sm), "l"(g), "r"(sz));
}
#define CP_COMMIT()  asm volatile("cp.async.commit_group;" ::: "memory")
#define CP_WAIT(n)   asm volatile("cp.async.wait_group %0;" :: "n"(n) : "memory")

// ---------------- edge dtype ----------------
__device__ __forceinline__ int edge_src(const void* p, int e) {
    return g_is64 ? (int)((const long long*)p)[e] : ((const int*)p)[e];
}
__device__ __forceinline__ int edge_dst(const void* p, int e) {
    return g_is64 ? (int)((const long long*)p)[N_EDGES + e] : ((const int*)p)[N_EDGES + e];
}

// ---------------- stream-B head: deg zero + scan-flag zero + dtype detect ----------------
__global__ void zero_detect_kernel(const int* __restrict__ e32) {
    int i = blockIdx.x * blockDim.x + threadIdx.x;
    if (i < N_NODES) g_deg[i] = 0;
    if (i < 128) { g_bflag[i] = 0; }
    if (i == 0) {
        int nz = 0;
        for (int q = 0; q < 64; q++) nz |= e32[2 * q + 1];
        g_is64 = (nz == 0) ? 1 : 0;
    }
}

// ---------------- fused: x->fp16 + weight transpose ----------------
#define NXT (N_NODES * 32)
__global__ void prep_convw_kernel(const float* __restrict__ x,
                                  const float* __restrict__ W1l, const float* __restrict__ W1r,
                                  const float* __restrict__ W2l, const float* __restrict__ W2r) {
    int t = blockIdx.x * blockDim.x + threadIdx.x;
    if (t < NXT) {
        int row = t >> 5, q = t & 31;
        float4 v = ((const float4*)x)[(size_t)row * 32 + q];
        *(uint2*)(g_Xh + (size_t)row * 128 + q * 4) = make_uint2(
            pack_h2(__float2half(v.x), __float2half(v.y)),
            pack_h2(__float2half(v.z), __float2half(v.w)));
    } else {
        int idx = t - NXT;
        if (idx < 256 * 256) {
            int n = idx >> 8, k = idx & 255;
            float v = (k < 128) ? W1l[(size_t)k * 256 + n] : W1r[(size_t)(k - 128) * 256 + n];
            g_W1t[idx] = __float2half(v);
        } else if (idx < 256 * 256 + 96 * 256) {
            int j = idx - 256 * 256;
            int n = j >> 8, k = j & 255;
            float v = 0.f;
            if (n < 47) v = W2l[(size_t)k * 47 + n];
            else if (n >= 48 && n < 95) v = W2r[(size_t)k * 47 + (n - 48)];
            g_W2t[j] = __float2half(v);
        }
    }
}

// ---------------- CSR build (per-edge, max parallelism) ----------------
__global__ void hist_kernel(const void* __restrict__ ei) {
    int e = blockIdx.x * blockDim.x + threadIdx.x;
    if (e < N_EDGES) atomicAdd(&g_deg[edge_dst(ei, e)], 1);
}

// single-pass scan: local block scan + publish block sum + poll predecessors.
#define SCAN_B 1024
__global__ void scan_fused_kernel() {
    __shared__ int sm[SCAN_B];
    __shared__ int base_s;
    int tid = threadIdx.x;
    int b = blockIdx.x;
    int i = b * SCAN_B + tid;
    int d = (i < N_NODES) ? g_deg[i] : 0;
    sm[tid] = d;
    __syncthreads();
    for (int off = 1; off < SCAN_B; off <<= 1) {
        int t = (tid >= off) ? sm[tid - off] : 0;
        __syncthreads();
        sm[tid] += t;
        __syncthreads();
    }
    int incl = sm[tid];
    if (tid == SCAN_B - 1) {
        g_bsum[b] = incl;
        __threadfence();
        atomicExch(&g_bflag[b], 1);
    }
    if (tid == 0) base_s = 0;
    __syncthreads();
    if (tid < b) {
        while (atomicAdd(&g_bflag[tid], 0) == 0) { }
        atomicAdd(&base_s, g_bsum[tid]);
    }
    __syncthreads();
    int base = base_s;
    if (i < N_NODES) {
        int v = incl + base;
        g_off[i + 1] = v;
        g_cur[i] = v - d;
    }
    if (i == 0) g_off[0] = 0;
}

__global__ void scatter_kernel(const void* __restrict__ ei) {
    int e = blockIdx.x * blockDim.x + threadIdx.x;
    if (e < N_EDGES) {
        int s = edge_src(ei, e);
        int d = edge_dst(ei, e);
        int p = atomicAdd(&g_cur[d], 1);
        g_srcs[p] = s;
    }
}

// ---------------- agg1: mean of fp16 x over in-neighbors -> g_M (MLP-4 inner loop) ----
__global__ void agg1_kernel() {
    int w = (blockIdx.x * blockDim.x + threadIdx.x) >> 5;
    if (w >= N_NODES) return;
    int lane = threadIdx.x & 31;
    int beg = g_off[w], end = g_off[w + 1];
    const uint2* xv = (const uint2*)g_Xh;
    float4 acc = make_float4(0.f, 0.f, 0.f, 0.f);
    for (int e0 = beg; e0 < end; e0 += 32) {
        int me = e0 + lane;
        int s = (me < end) ? g_srcs[me] : 0;
        int cnt = min(32, end - e0);
        int j = 0;
        for (; j + 4 <= cnt; j += 4) {
            int s0 = __shfl_sync(0xffffffffu, s, j);
            int s1 = __shfl_sync(0xffffffffu, s, j + 1);
            int s2 = __shfl_sync(0xffffffffu, s, j + 2);
            int s3 = __shfl_sync(0xffffffffu, s, j + 3);
            uint2 p0 = xv[(size_t)s0 * 32 + lane];
            uint2 p1 = xv[(size_t)s1 * 32 + lane];
            uint2 p2 = xv[(size_t)s2 * 32 + lane];
            uint2 p3 = xv[(size_t)s3 * 32 + lane];
            float2 a0 = __half22float2(*(__half2*)&p0.x), b0 = __half22float2(*(__half2*)&p0.y);
            acc.x += a0.x; acc.y += a0.y; acc.z += b0.x; acc.w += b0.y;
            float2 a1 = __half22float2(*(__half2*)&p1.x), b1v = __half22float2(*(__half2*)&p1.y);
            acc.x += a1.x; acc.y += a1.y; acc.z += b1v.x; acc.w += b1v.y;
            float2 a2 = __half22float2(*(__half2*)&p2.x), b2v = __half22float2(*(__half2*)&p2.y);
            acc.x += a2.x; acc.y += a2.y; acc.z += b2v.x; acc.w += b2v.y;
            float2 a3 = __half22float2(*(__half2*)&p3.x), b3v = __half22float2(*(__half2*)&p3.y);
            acc.x += a3.x; acc.y += a3.y; acc.z += b3v.x; acc.w += b3v.y;
        }
        for (; j < cnt; j++) {
            int sj = __shfl_sync(0xffffffffu, s, j);
            uint2 p = xv[(size_t)sj * 32 + lane];
            float2 a = __half22float2(*(__half2*)&p.x);
            float2 b = __half22float2(*(__half2*)&p.y);
            acc.x += a.x; acc.y += a.y; acc.z += b.x; acc.w += b.y;
        }
    }
    float inv = 1.f / (float)max(end - beg, 1);
    *(uint2*)(g_M + (size_t)w * 128 + lane * 4) = make_uint2(
        pack_h2(__float2half(acc.x * inv), __float2half(acc.y * inv)),
        pack_h2(__float2half(acc.z * inv), __float2half(acc.w * inv)));
}

// ---------------- FUSED GEMM: H = relu([M|X]@W1^T + b1) kept in smem,
//                  then [yl|yr] = H @ W2^T  (single kernel, no H round-trip)
__global__ __launch_bounds__(256) void fused_gemm(const float* __restrict__ b1) {
    extern __shared__ __align__(1024) char smm[];
    const int BUF = 49152, AO = 0, WO = 16384;
    const int HBASE = 0, W2BASE = 65536, W2BUF = 12288;
    uint32_t sb = smem_u32(smm);
    int tid = threadIdx.x, l = tid & 31, wid = tid >> 5;
    int wm = wid & 3, wn = wid >> 2;
    int rowBase = blockIdx.x * 128;

    float acc[2][16][4];
#pragma unroll
    for (int i = 0; i < 2; i++)
#pragma unroll
        for (int j = 0; j < 16; j++)
#pragma unroll
            for (int q = 0; q < 4; q++) acc[i][j][q] = 0.f;

    int a_r0 = wm * 32 + (l & 7) + (l & 8);
    int a_kl = (l >> 4) * 8;
    int b_r0 = wn * 128 + (l & 7) + ((l >> 4) & 1) * 8;
    int b_kl = ((l >> 3) & 1) * 8;

    auto load_chunk = [&](int c, int buf) {
#pragma unroll
        for (int hh = 0; hh < 4; hh++) {
            int i = tid + hh * 256;
            int r = i >> 3, s = i & 7;
            uint32_t so = swz(r * 128 + s * 16);
            int row = rowBase + r;
            bool ok = row < N_NODES;
            int rc = ok ? row : 0;
            const char* asrc = (c < 2)
                ? ((const char*)g_M + (size_t)rc * 256 + c * 128 + s * 16)
                : ((const char*)g_Xh + (size_t)rc * 256 + (c - 2) * 128 + s * 16);
            cp16(sb + buf * BUF + AO + so, asrc, ok);
        }
#pragma unroll
        for (int hh = 0; hh < 8; hh++) {
            int i = tid + hh * 256;
            int r = i >> 3, s = i & 7;
            uint32_t so = swz(r * 128 + s * 16);
            cp16(sb + buf * BUF + WO + so,
                 (const char*)g_W1t + (size_t)r * 512 + c * 128 + s * 16, true);
        }
        CP_COMMIT();
    };

    load_chunk(0, 0);
#pragma unroll
    for (int c = 0; c < 4; c++) {
        if (c < 3) { load_chunk(c + 1, (c + 1) & 1); CP_WAIT(1); }
        else CP_WAIT(0);
        __syncthreads();
        uint32_t bbase = sb + (c & 1) * BUF;
#pragma unroll
        for (int ks = 0; ks < 4; ks++) {
            uint32_t ah[2][4];
#pragma unroll
            for (int mf = 0; mf < 2; mf++)
                ldsm4(ah[mf], bbase + AO + swz((a_r0 + mf * 16) * 128 + (ks * 16 + a_kl) * 2));
#pragma unroll
            for (int nf2 = 0; nf2 < 8; nf2++) {
                uint32_t off = swz((b_r0 + nf2 * 16) * 128 + (ks * 16 + b_kl) * 2);
                uint32_t bh[4];
                ldsm4(bh, bbase + WO + off);
#pragma unroll
                for (int half = 0; half < 2; half++) {
                    int nf = nf2 * 2 + half;
                    uint32_t bhp[2] = {bh[half * 2], bh[half * 2 + 1]};
#pragma unroll
                    for (int mf = 0; mf < 2; mf++)
                        mma_f16(acc[mf][nf], ah[mf], bhp);
                }
            }
        }
        __syncthreads();
    }

    // ---- phase 2 setup: prefetch W2 chunk 0, store H (relu+bias, fp16) to smem ----
    auto load_w2 = [&](int c, int buf) {
#pragma unroll
        for (int hh = 0; hh < 3; hh++) {
            int i = tid + hh * 256;
            int r = i >> 3, s = i & 7;
            cp16(sb + W2BASE + buf * W2BUF + swz(r * 128 + s * 16),
                 (const char*)g_W2t + (size_t)r * 512 + c * 128 + s * 16, true);
        }
        CP_COMMIT();
    };
    load_w2(0, 0);

    {
        int er0l = wm * 32 + (l >> 2);       // local row
        int ec0 = wn * 128 + (l & 3) * 2;
#pragma unroll
        for (int nf = 0; nf < 16; nf++) {
            int col = ec0 + nf * 8;
            int chunk = col >> 6;
            int k = col & 63;
            float bx = __ldg(b1 + col), by = __ldg(b1 + col + 1);
#pragma unroll
            for (int mf = 0; mf < 2; mf++) {
#pragma unroll
                for (int half = 0; half < 2; half++) {
                    int r = er0l + mf * 16 + half * 8;
                    float v0 = fmaxf(acc[mf][nf][half * 2 + 0] + bx, 0.f);
                    float v1 = fmaxf(acc[mf][nf][half * 2 + 1] + by, 0.f);
                    *(uint32_t*)(smm + HBASE + chunk * 16384 + swz(r * 128 + k * 2)) =
                        pack_h2(__float2half(v0), __float2half(v1));
                }
            }
        }
    }
    CP_WAIT(0);
    __syncthreads();

    // ---- phase 2: [yl|yr] = H @ W2^T (N=96), warp tile 32x48 ----
    float acc2[2][6][4];
#pragma unroll
    for (int i = 0; i < 2; i++)
#pragma unroll
        for (int j = 0; j < 6; j++)
#pragma unroll
            for (int q = 0; q < 4; q++) acc2[i][j][q] = 0.f;

    int b2_r0 = wn * 48 + (l & 7) + ((l >> 4) & 1) * 8;

#pragma unroll
    for (int c = 0; c < 4; c++) {
        if (c < 3) load_w2(c + 1, (c + 1) & 1);
        uint32_t hbase = sb + HBASE + c * 16384;
        uint32_t wbase = sb + W2BASE + (c & 1) * W2BUF;
#pragma unroll
        for (int ks = 0; ks < 4; ks++) {
            uint32_t ah[2][4];
#pragma unroll
            for (int mf = 0; mf < 2; mf++)
                ldsm4(ah[mf], hbase + swz((a_r0 + mf * 16) * 128 + (ks * 16 + a_kl) * 2));
#pragma unroll
            for (int nf2 = 0; nf2 < 3; nf2++) {
                uint32_t off = swz((b2_r0 + nf2 * 16) * 128 + (ks * 16 + b_kl) * 2);
                uint32_t bh[4];
                ldsm4(bh, wbase + off);
#pragma unroll
                for (int half = 0; half < 2; half++) {
                    int nf = nf2 * 2 + half;
                    uint32_t bhp[2] = {bh[half * 2], bh[half * 2 + 1]};
#pragma unroll
                    for (int mf = 0; mf < 2; mf++)
                        mma_f16(acc2[mf][nf], ah[mf], bhp);
                }
            }
        }
        if (c < 3) { CP_WAIT(0); __syncthreads(); }
    }

    // epilogue: yl (fp16) / yr (fp32)
    int er0 = rowBase + wm * 32 + (l >> 2);
    int ec0 = wn * 48 + (l & 3) * 2;
#pragma unroll
    for (int nf = 0; nf < 6; nf++) {
        int col = ec0 + nf * 8;
#pragma unroll
        for (int mf = 0; mf < 2; mf++) {
#pragma unroll
            for (int half = 0; half < 2; half++) {
                int row = er0 + mf * 16 + half * 8;
                if (row >= N_NODES) continue;
                float v0 = acc2[mf][nf][half * 2 + 0];
                float v1 = acc2[mf][nf][half * 2 + 1];
                if (col < 48)
                    *(uint32_t*)(g_ylh + (size_t)row * OUTP + col) =
                        pack_h2(__float2half(v0), __float2half(v1));
                else
                    *(float2*)(g_yr + (size_t)row * OUTP + col - 48) = make_float2(v0, v1);
            }
        }
    }
}

// ---------------- final: mean-agg of ylh (fp16) + b2 + yr + log_softmax (MLP-4) ----
__global__ void final_kernel(const float* __restrict__ b2, float* __restrict__ out) {
    int w = (blockIdx.x * blockDim.x + threadIdx.x) >> 5;
    if (w >= N_NODES) return;
    int lane = threadIdx.x & 31;
    int beg = g_off[w], end = g_off[w + 1];
    float inv = 1.f / (float)max(end - beg, 1);
    bool act = lane < 24;
    const uint32_t* ylv = (const uint32_t*)g_ylh;
    float2 acc = make_float2(0.f, 0.f);
    for (int e0 = beg; e0 < end; e0 += 32) {
        int me = e0 + lane;
        int s = (me < end) ? g_srcs[me] : 0;
        int cnt = min(32, end - e0);
        int j = 0;
        for (; j + 4 <= cnt; j += 4) {
            int s0 = __shfl_sync(0xffffffffu, s, j);
            int s1 = __shfl_sync(0xffffffffu, s, j + 1);
            int s2 = __shfl_sync(0xffffffffu, s, j + 2);
            int s3 = __shfl_sync(0xffffffffu, s, j + 3);
            if (act) {
                uint32_t p0 = ylv[(size_t)s0 * 24 + lane];
                uint32_t p1 = ylv[(size_t)s1 * 24 + lane];
                uint32_t p2 = ylv[(size_t)s2 * 24 + lane];
                uint32_t p3 = ylv[(size_t)s3 * 24 + lane];
                float2 v0 = __half22float2(*(__half2*)&p0);
                acc.x += v0.x; acc.y += v0.y;
                float2 v1 = __half22float2(*(__half2*)&p1);
                acc.x += v1.x; acc.y += v1.y;
                float2 v2 = __half22float2(*(__half2*)&p2);
                acc.x += v2.x; acc.y += v2.y;
                float2 v3 = __half22float2(*(__half2*)&p3);
                acc.x += v3.x; acc.y += v3.y;
            }
        }
        for (; j < cnt; j++) {
            int sj = __shfl_sync(0xffffffffu, s, j);
            if (act) {
                uint32_t p = ylv[(size_t)sj * 24 + lane];
                float2 v = __half22float2(*(__half2*)&p);
                acc.x += v.x; acc.y += v.y;
            }
        }
    }
    int c0 = lane * 2, c1 = lane * 2 + 1;
    float z0 = -1e30f, z1 = -1e30f;
    if (c0 < OUT_C) z0 = acc.x * inv + b2[c0] + g_yr[(size_t)w * OUTP + c0];
    if (c1 < OUT_C) z1 = acc.y * inv + b2[c1] + g_yr[(size_t)w * OUTP + c1];
    float m = fmaxf(z0, z1);
#pragma unroll
    for (int o = 16; o > 0; o >>= 1) m = fmaxf(m, __shfl_xor_sync(0xffffffffu, m, o));
    float s = 0.f;
    if (c0 < OUT_C) s += expf(z0 - m);
    if (c1 < OUT_C) s += expf(z1 - m);
#pragma unroll
    for (int o = 16; o > 0; o >>= 1) s += __shfl_xor_sync(0xffffffffu, s, o);
    float l = logf(s);
    if (c0 < OUT_C) out[(size_t)w * OUT_C + c0] = z0 - m - l;
    if (c1 < OUT_C) out[(size_t)w * OUT_C + c1] = z1 - m - l;
}

// ---------------- launch ----------------
extern "C" void kernel_launch(void* const* d_in, const int* in_sizes, int n_in,
                              void* d_out, int out_size) {
    const float* x   = (const float*)d_in[0];
    const void*  ei  = d_in[1];
    const float* W1l = (const float*)d_in[2];
    const float* b1  = (const float*)d_in[3];
    const float* W1r = (const float*)d_in[4];
    const float* W2l = (const float*)d_in[5];
    const float* b2  = (const float*)d_in[6];
    const float* W2r = (const float*)d_in[7];
    float* out = (float*)d_out;

    static cudaStream_t s2 = nullptr;
    static cudaEvent_t evF = nullptr, evS = nullptr;
    if (!s2) {
        cudaStreamCreate(&s2);
        cudaEventCreateWithFlags(&evF, cudaEventDisableTiming);
        cudaEventCreateWithFlags(&evS, cudaEventDisableTiming);
    }

    const int SMEM = 98304;
    static bool attr_set = false;
    if (!attr_set) {
        cudaFuncSetAttribute(fused_gemm, cudaFuncAttributeMaxDynamicSharedMemorySize, SMEM);
        attr_set = true;
    }

    const int scan_blocks = (N_NODES + SCAN_B - 1) / SCAN_B;   // 98
    const int tiles = (N_NODES + 127) / 128;                    // 782

    // fork: s2 builds CSR while stream 0 converts x and weights
    cudaEventRecord(evF, 0);
    cudaStreamWaitEvent(s2, evF, 0);

    zero_detect_kernel<<<(N_NODES + 255) / 256, 256, 0, s2>>>((const int*)ei);
    hist_kernel<<<(N_EDGES + 255) / 256, 256, 0, s2>>>(ei);
    scan_fused_kernel<<<scan_blocks, SCAN_B, 0, s2>>>();
    scatter_kernel<<<(N_EDGES + 255) / 256, 256, 0, s2>>>(ei);
    cudaEventRecord(evS, s2);           // CSR complete

    prep_convw_kernel<<<(NXT + 256 * 256 + 96 * 256 + 255) / 256, 256>>>(x, W1l, W1r, W2l, W2r);

    // join: agg needs CSR; fused gemm needs agg + prep (in-stream order)
    cudaStreamWaitEvent(0, evS, 0);
    agg1_kernel<<<(N_NODES * 32 + 255) / 256, 256>>>();
    fused_gemm<<<tiles, 256, SMEM>>>(b1);
    final_kernel<<<(N_NODES * 32 + 255) / 256, 256>>>(b2, out);
}